// round 8
// baseline (speedup 1.0000x reference)
#include <cuda_runtime.h>
#include <cuda_bf16.h>
#include <cuda_fp8.h>
#include <cstdint>

// Problem constants: B=8, N=1024, C=1024, H=16, D=64
#define BB 8
#define NN 1024
#define CC 1024
#define HH 16
#define DD 64
#define SCALE 0.125f

// ---------------------------------------------------------------------------
// Scratch
// A-side operands (x, attention-out): A16 = bf16(a)*16, A8h = e4m3(bf16(a)/4),
//   A8l = e4m3((a - bf16(a))*64)
// B-side operands (weights): B16 = bf16(w)*16, B8l = e4m3((w - bf16(w))*1024),
//   B8h = e4m3(bf16(w)*4)
// All three MMA terms carry scale 256 and share one fp32 accumulator.
// ---------------------------------------------------------------------------
__device__ __nv_bfloat16 g_qhi[BB*HH*NN*DD];  // [bh][n][d], q pre-scaled by 1/8
__device__ __nv_bfloat16 g_qlo[BB*HH*NN*DD];
__device__ __nv_bfloat16 g_khi[BB*HH*NN*DD];
__device__ __nv_bfloat16 g_klo[BB*HH*NN*DD];
__device__ __nv_bfloat16 g_vhi[BB*HH*NN*DD];
__device__ __nv_bfloat16 g_vlo[BB*HH*NN*DD];

__device__ __nv_bfloat16 g_x16[BB*NN*CC];
__device__ uint8_t       g_x8h[BB*NN*CC];
__device__ uint8_t       g_x8l[BB*NN*CC];
__device__ __nv_bfloat16 g_wi16[3*CC*CC];
__device__ uint8_t       g_wi8l[3*CC*CC];
__device__ uint8_t       g_wi8h[3*CC*CC];
__device__ __nv_bfloat16 g_wo16[CC*CC];
__device__ uint8_t       g_wo8l[CC*CC];
__device__ uint8_t       g_wo8h[CC*CC];
__device__ __nv_bfloat16 g_o16[BB*NN*CC];
__device__ uint8_t       g_o8h[BB*NN*CC];
__device__ uint8_t       g_o8l[BB*NN*CC];

// ---------------------------------------------------------------------------
// Portable (sm_80+/sm_89+) tensor-core helpers
// ---------------------------------------------------------------------------
__device__ __forceinline__ uint32_t smem_to_u32(const void* p) {
    uint32_t a;
    asm("{ .reg .u64 t; cvta.to.shared.u64 t, %1; cvt.u32.u64 %0, t; }"
        : "=r"(a) : "l"(p));
    return a;
}
__device__ __forceinline__ void ldsm_x4(uint32_t r[4], uint32_t addr) {
    asm volatile("ldmatrix.sync.aligned.m8n8.x4.shared.b16 {%0,%1,%2,%3}, [%4];"
        : "=r"(r[0]), "=r"(r[1]), "=r"(r[2]), "=r"(r[3]) : "r"(addr));
}
__device__ __forceinline__ void ldsm_x4_t(uint32_t r[4], uint32_t addr) {
    asm volatile("ldmatrix.sync.aligned.m8n8.x4.trans.shared.b16 {%0,%1,%2,%3}, [%4];"
        : "=r"(r[0]), "=r"(r[1]), "=r"(r[2]), "=r"(r[3]) : "r"(addr));
}
__device__ __forceinline__ void mma16816(float c[4], const uint32_t a[4],
                                         const uint32_t b[2]) {
    asm volatile(
        "mma.sync.aligned.m16n8k16.row.col.f32.bf16.bf16.f32 "
        "{%0,%1,%2,%3}, {%4,%5,%6,%7}, {%8,%9}, {%0,%1,%2,%3};"
        : "+f"(c[0]), "+f"(c[1]), "+f"(c[2]), "+f"(c[3])
        : "r"(a[0]), "r"(a[1]), "r"(a[2]), "r"(a[3]), "r"(b[0]), "r"(b[1]));
}
// e4m3 mma (sm_89 legacy shape), fp32 accumulate — shares accs with bf16 mma
__device__ __forceinline__ void mma_fp8(float c[4], const uint32_t a[4],
                                        const uint32_t b[2]) {
    asm volatile(
        "mma.sync.aligned.m16n8k32.row.col.f32.e4m3.e4m3.f32 "
        "{%0,%1,%2,%3}, {%4,%5,%6,%7}, {%8,%9}, {%0,%1,%2,%3};"
        : "+f"(c[0]), "+f"(c[1]), "+f"(c[2]), "+f"(c[3])
        : "r"(a[0]), "r"(a[1]), "r"(a[2]), "r"(a[3]), "r"(b[0]), "r"(b[1]));
}
#define CP_ASYNC16(sa, ga) \
    asm volatile("cp.async.cg.shared.global [%0], [%1], 16;" \
                 :: "r"(sa), "l"(ga) : "memory")
#define CP_COMMIT() asm volatile("cp.async.commit_group;" ::: "memory")
#define CP_WAIT1()  asm volatile("cp.async.wait_group 1;" ::: "memory")
#define CP_WAIT0()  asm volatile("cp.async.wait_group 0;" ::: "memory")

__device__ __forceinline__ uint32_t swz(int row, int cx) {
    return (uint32_t)(row * 128) + ((uint32_t)(cx ^ (row & 7)) << 4);
}
__device__ __forceinline__ uint8_t f2fp8(float v) {
    return (uint8_t)__nv_cvt_float_to_fp8(v, __NV_SATFINITE, __NV_E4M3);
}

// ---------------------------------------------------------------------------
// Operand-prep kernels
// ---------------------------------------------------------------------------
__global__ void __launch_bounds__(256) split_a_kernel(
        const float* __restrict__ src, __nv_bfloat16* __restrict__ o16,
        uint8_t* __restrict__ o8h, uint8_t* __restrict__ o8l, int n) {
    int i = blockIdx.x * 256 + threadIdx.x;
    if (i < n) {
        float x = src[i];
        __nv_bfloat16 h = __float2bfloat16(x);
        float hf = __bfloat162float(h);
        o16[i] = __float2bfloat16(hf * 16.f);
        o8h[i] = f2fp8(hf * 0.25f);
        o8l[i] = f2fp8((x - hf) * 64.f);
    }
}
__global__ void __launch_bounds__(256) split_b_kernel(
        const float* __restrict__ src, __nv_bfloat16* __restrict__ o16,
        uint8_t* __restrict__ o8l, uint8_t* __restrict__ o8h, int n) {
    int i = blockIdx.x * 256 + threadIdx.x;
    if (i < n) {
        float w = src[i];
        __nv_bfloat16 h = __float2bfloat16(w);
        float hf = __bfloat162float(h);
        o16[i] = __float2bfloat16(hf * 16.f);
        o8l[i] = f2fp8((w - hf) * 1024.f);
        o8h[i] = f2fp8(hf * 4.f);
    }
}

// ---------------------------------------------------------------------------
// Hybrid bf16/fp8 GEMM: D = (A @ B^T)/256 + bias.
// Tile 128x128, K-chunk 32. Smem row (128B) = [32 bf16 hi | 32B A8h | 32B A8l]
// (B rows: [32 bf16 hi | 32B B8l | 32B B8h]). Per chunk per warp:
//   2x k16 bf16 MMA (hi.hi x 16 tiles) + 2x k32 fp8 MMA (cross x 16 tiles).
// 3-stage cp.async (96KB) -> 2 CTAs/SM.
// ---------------------------------------------------------------------------
#define STG_STRIDE 32768
#define T_B 16384
#define GEMM_SMEM (3 * STG_STRIDE)
#define INV256 0.00390625f

__global__ void __launch_bounds__(256, 2) gemm_mma_kernel(
        const __nv_bfloat16* __restrict__ A16, const uint8_t* __restrict__ A8h,
        const uint8_t* __restrict__ A8l,
        const __nv_bfloat16* __restrict__ B16, const uint8_t* __restrict__ B8l,
        const uint8_t* __restrict__ B8h,
        const float* __restrict__ bias, float* __restrict__ outp, int mode) {
    extern __shared__ char smem[];
    const uint32_t sbase = smem_to_u32(smem);
    const int tid = threadIdx.x;
    const int wid = tid >> 5, lane = tid & 31;
    const int wm = wid >> 2, wn = wid & 3;
    const int row0 = blockIdx.y * 128, col0 = blockIdx.x * 128;
    const int mat = lane >> 3, rin = lane & 7;

    float cacc[4][4][4];
#pragma unroll
    for (int mi = 0; mi < 4; mi++)
#pragma unroll
        for (int nj = 0; nj < 4; nj++)
#pragma unroll
            for (int e = 0; e < 4; e++) cacc[mi][nj][e] = 0.f;

    // loader: 2048 16B chunks/stage; cx 0-3 bf16-hi, 4-5 fp8 #1, 6-7 fp8 #2
    auto issue = [&](int stage, int c) {
        const int k0 = c * 32;
        const uint32_t sst = sbase + stage * STG_STRIDE;
#pragma unroll
        for (int p = 0; p < 4; p++) {
            int id = tid + p * 256;
            int row = id >> 3, cx = id & 7;
            uint32_t dst = swz(row, cx);
            size_t ra = (size_t)(row0 + row) * 1024;
            size_t rb = (size_t)(col0 + row) * 1024;
            const char* pa;
            const char* pb;
            if (cx < 4) {
                pa = (const char*)(A16 + ra + k0 + cx * 8);
                pb = (const char*)(B16 + rb + k0 + cx * 8);
            } else if (cx < 6) {
                pa = (const char*)(A8h + ra + k0 + (cx - 4) * 16);
                pb = (const char*)(B8l + rb + k0 + (cx - 4) * 16);
            } else {
                pa = (const char*)(A8l + ra + k0 + (cx - 6) * 16);
                pb = (const char*)(B8h + rb + k0 + (cx - 6) * 16);
            }
            CP_ASYNC16(sst + dst, pa);
            CP_ASYNC16(sst + T_B + dst, pb);
        }
        CP_COMMIT();
    };

    auto compute = [&](int stage) {
        const uint32_t sA = sbase + stage * STG_STRIDE;
        // ---- bf16 hi.hi: 2 k16 steps ----
#pragma unroll
        for (int s = 0; s < 2; s++) {
            uint32_t ah[4][4], bhf[4][2];
            const int cxh = s * 2 + (mat >> 1);
#pragma unroll
            for (int mi = 0; mi < 4; mi++) {
                int row = wm * 64 + mi * 16 + rin + (mat & 1) * 8;
                ldsm_x4(ah[mi], sA + swz(row, cxh));
            }
#pragma unroll
            for (int nf = 0; nf < 2; nf++) {
                int row = wn * 32 + nf * 16 + rin + (mat & 1) * 8;
                uint32_t t[4];
                ldsm_x4(t, sA + T_B + swz(row, cxh));
                bhf[nf*2][0] = t[0]; bhf[nf*2][1] = t[2];
                bhf[nf*2+1][0] = t[1]; bhf[nf*2+1][1] = t[3];
            }
#pragma unroll
            for (int mi = 0; mi < 4; mi++)
#pragma unroll
                for (int nj = 0; nj < 4; nj++)
                    mma16816(cacc[mi][nj], ah[mi], bhf[nj]);
        }
        // ---- fp8 cross: step0 = A8h x B8l, step1 = A8l x B8h ----
#pragma unroll
        for (int st = 0; st < 2; st++) {
            uint32_t ac[4][4], bc[4][2];
            const int c0 = 4 + st * 2;
#pragma unroll
            for (int mi = 0; mi < 4; mi++) {
                int row = wm * 64 + mi * 16 + rin + (mat & 1) * 8;
                int cxx = c0 + (mat >> 1);
                ldsm_x4(ac[mi], sA + swz(row, cxx));
            }
            {
                // 4 n8 tiles per ldsm; one per k-byte half
                int row = wn * 32 + mat * 8 + rin;
                uint32_t t0[4], t1[4];
                ldsm_x4(t0, sA + T_B + swz(row, c0));
                ldsm_x4(t1, sA + T_B + swz(row, c0 + 1));
#pragma unroll
                for (int nj = 0; nj < 4; nj++) {
                    bc[nj][0] = t0[nj];
                    bc[nj][1] = t1[nj];
                }
            }
#pragma unroll
            for (int mi = 0; mi < 4; mi++)
#pragma unroll
                for (int nj = 0; nj < 4; nj++)
                    mma_fp8(cacc[mi][nj], ac[mi], bc[nj]);
        }
    };

    auto step = [&](int c, int stage, int nxt) {
        if (c < 31) CP_WAIT1(); else CP_WAIT0();
        __syncthreads();
        if (c + 2 < 32) issue(nxt, c + 2);
        compute(stage);
    };

    issue(0, 0); issue(1, 1);
#pragma unroll 1
    for (int cb = 0; cb < 30; cb += 3) {
        step(cb + 0, 0, 2);
        step(cb + 1, 1, 0);
        step(cb + 2, 2, 1);
    }
    step(30, 0, 2);
    step(31, 1, 0);

    const int g = lane >> 2, c4 = lane & 3;
#pragma unroll
    for (int mi = 0; mi < 4; mi++)
#pragma unroll
        for (int h2 = 0; h2 < 2; h2++) {
            int row = row0 + wm * 64 + mi * 16 + g + h2 * 8;
            int b = row >> 10, n_ = row & 1023;
#pragma unroll
            for (int nj = 0; nj < 4; nj++) {
                int col = col0 + wn * 32 + nj * 8 + c4 * 2;
                float v0 = cacc[mi][nj][h2 * 2 + 0] * INV256 + bias[col];
                float v1 = cacc[mi][nj][h2 * 2 + 1] * INV256 + bias[col + 1];
                if (mode == 0) {
                    int sec = col >> 10;
                    int ci = col & 1023;
                    int hh = ci >> 6, d = ci & 63;
                    if (sec == 0) { v0 *= SCALE; v1 *= SCALE; }
                    __nv_bfloat162 hi2 = __floats2bfloat162_rn(v0, v1);
                    float r0 = v0 - __bfloat162float(hi2.x);
                    float r1 = v1 - __bfloat162float(hi2.y);
                    __nv_bfloat162 lo2 = __floats2bfloat162_rn(r0, r1);
                    size_t idx = ((size_t)(((b * 16 + hh) << 10) | n_)) * 64 + d;
                    __nv_bfloat16 *dh = (sec == 0) ? g_qhi : (sec == 1) ? g_khi : g_vhi;
                    __nv_bfloat16 *dl = (sec == 0) ? g_qlo : (sec == 1) ? g_klo : g_vlo;
                    *(uint32_t*)&dh[idx] = *(uint32_t*)&hi2;
                    *(uint32_t*)&dl[idx] = *(uint32_t*)&lo2;
                } else {
                    float2 vv = make_float2(v0, v1);
                    *(float2*)&outp[(size_t)row * 1024 + col] = vv;
                }
            }
        }
}

// ---------------------------------------------------------------------------
// Tensor-core flash attention (bf16 3-term split, unchanged mainloop).
// Epilogue now emits out-proj A-operands (o16 / o8h / o8l).
// ---------------------------------------------------------------------------
#define AT_SQH 0
#define AT_SQL 16384
#define AT_ST0 32768
#define AT_KH 0
#define AT_KL 8192
#define AT_VH 16384
#define AT_VL 24576
#define ATTN_SMEM 98304

__global__ void __launch_bounds__(256, 2) attn_mma_kernel() {
    extern __shared__ char smem[];
    const uint32_t sbase = smem_to_u32(smem);
    const int tid = threadIdx.x;
    const int wid = tid >> 5, lane = tid & 31;
    const int bh = blockIdx.y, q0 = blockIdx.x * 128;
    const int b = bh >> 4, h = bh & 15;
    const int mat = lane >> 3, rin = lane & 7;
    const int g = lane >> 2, c4 = lane & 3;

    const __nv_bfloat16* __restrict__ qhp = g_qhi + (size_t)bh * NN * DD;
    const __nv_bfloat16* __restrict__ qlp = g_qlo + (size_t)bh * NN * DD;
    const __nv_bfloat16* __restrict__ khp = g_khi + (size_t)bh * NN * DD;
    const __nv_bfloat16* __restrict__ klp = g_klo + (size_t)bh * NN * DD;
    const __nv_bfloat16* __restrict__ vhp = g_vhi + (size_t)bh * NN * DD;
    const __nv_bfloat16* __restrict__ vlp = g_vlo + (size_t)bh * NN * DD;

#pragma unroll
    for (int p = 0; p < 4; p++) {
        int chunk = tid + p * 256;
        int row = chunk >> 3, cx = chunk & 7;
        uint32_t dst = swz(row, cx);
        size_t src = (size_t)(q0 + row) * 64 + cx * 8;
        CP_ASYNC16(sbase + AT_SQH + dst, qhp + src);
        CP_ASYNC16(sbase + AT_SQL + dst, qlp + src);
    }
    CP_COMMIT();

    auto issue_kv = [&](int st, int kt) {
        const uint32_t sb = sbase + AT_ST0 + st * 32768;
        const size_t base = (size_t)(kt * 64) * 64;
#pragma unroll
        for (int p = 0; p < 2; p++) {
            int chunk = tid + p * 256;
            int row = chunk >> 3, cx = chunk & 7;
            uint32_t dst = swz(row, cx);
            size_t src = base + (size_t)row * 64 + cx * 8;
            CP_ASYNC16(sb + AT_KH + dst, khp + src);
            CP_ASYNC16(sb + AT_KL + dst, klp + src);
            CP_ASYNC16(sb + AT_VH + dst, vhp + src);
            CP_ASYNC16(sb + AT_VL + dst, vlp + src);
        }
        CP_COMMIT();
    };
    issue_kv(0, 0);
    issue_kv(1, 1);

    float m0 = -1e30f, m1 = -1e30f, l0 = 0.f, l1 = 0.f;
    float oacc[8][4];
#pragma unroll
    for (int i = 0; i < 8; i++)
#pragma unroll
        for (int e = 0; e < 4; e++) oacc[i][e] = 0.f;

    auto astep = [&](int kt, int st) {
        if (kt < 15) CP_WAIT1(); else CP_WAIT0();
        __syncthreads();
        const uint32_t skv = sbase + AT_ST0 + st * 32768;

        float sacc[8][4];
#pragma unroll
        for (int i = 0; i < 8; i++)
#pragma unroll
            for (int e = 0; e < 4; e++) sacc[i][e] = 0.f;

#pragma unroll
        for (int s = 0; s < 4; s++) {
            const int cx = s * 2 + (mat >> 1);
            uint32_t qh[4], ql[4];
            {
                int row = wid * 16 + (mat & 1) * 8 + rin;
                uint32_t off = swz(row, cx);
                ldsm_x4(qh, sbase + AT_SQH + off);
                ldsm_x4(ql, sbase + AT_SQL + off);
            }
#pragma unroll
            for (int t = 0; t < 4; t++) {
                int krow = t * 16 + (mat & 1) * 8 + rin;
                uint32_t off = swz(krow, cx);
                uint32_t th[4], tl[4];
                ldsm_x4(th, skv + AT_KH + off);
                ldsm_x4(tl, skv + AT_KL + off);
                uint32_t bh0[2] = {th[0], th[2]}, bh1[2] = {th[1], th[3]};
                uint32_t bl0[2] = {tl[0], tl[2]}, bl1[2] = {tl[1], tl[3]};
                mma16816(sacc[2*t],   qh, bh0);
                mma16816(sacc[2*t+1], qh, bh1);
                mma16816(sacc[2*t],   qh, bl0);
                mma16816(sacc[2*t+1], qh, bl1);
                mma16816(sacc[2*t],   ql, bh0);
                mma16816(sacc[2*t+1], ql, bh1);
            }
        }

        float mx0 = -1e30f, mx1 = -1e30f;
#pragma unroll
        for (int i = 0; i < 8; i++) {
            mx0 = fmaxf(mx0, fmaxf(sacc[i][0], sacc[i][1]));
            mx1 = fmaxf(mx1, fmaxf(sacc[i][2], sacc[i][3]));
        }
        mx0 = fmaxf(mx0, __shfl_xor_sync(0xffffffffu, mx0, 1));
        mx0 = fmaxf(mx0, __shfl_xor_sync(0xffffffffu, mx0, 2));
        mx1 = fmaxf(mx1, __shfl_xor_sync(0xffffffffu, mx1, 1));
        mx1 = fmaxf(mx1, __shfl_xor_sync(0xffffffffu, mx1, 2));
        float mn0 = fmaxf(m0, mx0), mn1 = fmaxf(m1, mx1);
        float al0 = __expf(m0 - mn0), al1 = __expf(m1 - mn1);
        m0 = mn0; m1 = mn1;
        float rs0 = 0.f, rs1 = 0.f;
#pragma unroll
        for (int i = 0; i < 8; i++) {
            sacc[i][0] = __expf(sacc[i][0] - mn0);
            sacc[i][1] = __expf(sacc[i][1] - mn0);
            sacc[i][2] = __expf(sacc[i][2] - mn1);
            sacc[i][3] = __expf(sacc[i][3] - mn1);
            rs0 += sacc[i][0] + sacc[i][1];
            rs1 += sacc[i][2] + sacc[i][3];
        }
        rs0 += __shfl_xor_sync(0xffffffffu, rs0, 1);
        rs0 += __shfl_xor_sync(0xffffffffu, rs0, 2);
        rs1 += __shfl_xor_sync(0xffffffffu, rs1, 1);
        rs1 += __shfl_xor_sync(0xffffffffu, rs1, 2);
        l0 = l0 * al0 + rs0;
        l1 = l1 * al1 + rs1;
#pragma unroll
        for (int i = 0; i < 8; i++) {
            oacc[i][0] *= al0; oacc[i][1] *= al0;
            oacc[i][2] *= al1; oacc[i][3] *= al1;
        }

#pragma unroll
        for (int s = 0; s < 4; s++) {
            uint32_t ph[4], pl[4];
            {
                float e0 = sacc[2*s][0], e1 = sacc[2*s][1];
                float e2 = sacc[2*s][2], e3 = sacc[2*s][3];
                float f0 = sacc[2*s+1][0], f1 = sacc[2*s+1][1];
                float f2 = sacc[2*s+1][2], f3 = sacc[2*s+1][3];
                __nv_bfloat162 t0 = __floats2bfloat162_rn(e0, e1);
                __nv_bfloat162 t1 = __floats2bfloat162_rn(e2, e3);
                __nv_bfloat162 t2 = __floats2bfloat162_rn(f0, f1);
                __nv_bfloat162 t3 = __floats2bfloat162_rn(f2, f3);
                ph[0] = *(uint32_t*)&t0; ph[1] = *(uint32_t*)&t1;
                ph[2] = *(uint32_t*)&t2; ph[3] = *(uint32_t*)&t3;
                __nv_bfloat162 u0 = __floats2bfloat162_rn(
                    e0 - __bfloat162float(t0.x), e1 - __bfloat162float(t0.y));
                __nv_bfloat162 u1 = __floats2bfloat162_rn(
                    e2 - __bfloat162float(t1.x), e3 - __bfloat162float(t1.y));
                __nv_bfloat162 u2 = __floats2bfloat162_rn(
                    f0 - __bfloat162float(t2.x), f1 - __bfloat162float(t2.y));
                __nv_bfloat162 u3 = __floats2bfloat162_rn(
                    f2 - __bfloat162float(t3.x), f3 - __bfloat162float(t3.y));
                pl[0] = *(uint32_t*)&u0; pl[1] = *(uint32_t*)&u1;
                pl[2] = *(uint32_t*)&u2; pl[3] = *(uint32_t*)&u3;
            }
#pragma unroll
            for (int t = 0; t < 4; t++) {
                int vrow = s * 16 + (mat >> 1) * 8 + rin;
                int cxv = t * 2 + (mat & 1);
                uint32_t off = swz(vrow, cxv);
                uint32_t th[4], tl[4];
                ldsm_x4_t(th, skv + AT_VH + off);
                ldsm_x4_t(tl, skv + AT_VL + off);
                uint32_t vh0[2] = {th[0], th[2]}, vh1[2] = {th[1], th[3]};
                uint32_t vl0[2] = {tl[0], tl[2]}, vl1[2] = {tl[1], tl[3]};
                mma16816(oacc[2*t],   ph, vh0);
                mma16816(oacc[2*t+1], ph, vh1);
                mma16816(oacc[2*t],   ph, vl0);
                mma16816(oacc[2*t+1], ph, vl1);
                mma16816(oacc[2*t],   pl, vh0);
                mma16816(oacc[2*t+1], pl, vh1);
            }
        }
        __syncthreads();
        if (kt + 2 < 16) issue_kv(st, kt + 2);
    };

#pragma unroll 1
    for (int kt = 0; kt < 16; kt += 2) {
        astep(kt, 0);
        astep(kt + 1, 1);
    }

    // epilogue: normalize and emit out-proj A-operands into [B*N, C]
    float inv0 = 1.f / l0, inv1 = 1.f / l1;
    int r0 = q0 + wid * 16 + g;
    int r1 = r0 + 8;
#pragma unroll
    for (int nj = 0; nj < 8; nj++) {
        int col = h * 64 + nj * 8 + c4 * 2;
#pragma unroll
        for (int half = 0; half < 2; half++) {
            float inv = half ? inv1 : inv0;
            int r = half ? r1 : r0;
            float v0 = oacc[nj][half * 2 + 0] * inv;
            float v1 = oacc[nj][half * 2 + 1] * inv;
            __nv_bfloat16 h0 = __float2bfloat16(v0);
            __nv_bfloat16 h1 = __float2bfloat16(v1);
            float hf0 = __bfloat162float(h0), hf1 = __bfloat162float(h1);
            size_t idx = (size_t)(b * 1024 + r) * 1024 + col;
            __nv_bfloat162 s16 = __floats2bfloat162_rn(hf0 * 16.f, hf1 * 16.f);
            *(uint32_t*)&g_o16[idx] = *(uint32_t*)&s16;
            g_o8h[idx]     = f2fp8(hf0 * 0.25f);
            g_o8h[idx + 1] = f2fp8(hf1 * 0.25f);
            g_o8l[idx]     = f2fp8((v0 - hf0) * 64.f);
            g_o8l[idx + 1] = f2fp8((v1 - hf1) * 64.f);
        }
    }
}

// ---------------------------------------------------------------------------
extern "C" void kernel_launch(void* const* d_in, const int* in_sizes, int n_in,
                              void* d_out, int out_size) {
    const float* x     = (const float*)d_in[0];
    const float* w_in  = (const float*)d_in[1];
    const float* b_in  = (const float*)d_in[2];
    const float* w_out = (const float*)d_in[3];
    const float* b_out = (const float*)d_in[4];
    float* out = (float*)d_out;

    static bool attr_set = false;
    if (!attr_set) {
        cudaFuncSetAttribute(gemm_mma_kernel,
                             cudaFuncAttributeMaxDynamicSharedMemorySize, GEMM_SMEM);
        cudaFuncSetAttribute(attn_mma_kernel,
                             cudaFuncAttributeMaxDynamicSharedMemorySize, ATTN_SMEM);
        attr_set = true;
    }

    __nv_bfloat16 *x16, *wi16, *wo16, *o16;
    uint8_t *x8h, *x8l, *wi8l, *wi8h, *wo8l, *wo8h, *o8h, *o8l;
    cudaGetSymbolAddress((void**)&x16,  g_x16);
    cudaGetSymbolAddress((void**)&x8h,  g_x8h);
    cudaGetSymbolAddress((void**)&x8l,  g_x8l);
    cudaGetSymbolAddress((void**)&wi16, g_wi16);
    cudaGetSymbolAddress((void**)&wi8l, g_wi8l);
    cudaGetSymbolAddress((void**)&wi8h, g_wi8h);
    cudaGetSymbolAddress((void**)&wo16, g_wo16);
    cudaGetSymbolAddress((void**)&wo8l, g_wo8l);
    cudaGetSymbolAddress((void**)&wo8h, g_wo8h);
    cudaGetSymbolAddress((void**)&o16,  g_o16);
    cudaGetSymbolAddress((void**)&o8h,  g_o8h);
    cudaGetSymbolAddress((void**)&o8l,  g_o8l);

    // 1) operand prep
    split_a_kernel<<<(BB*NN*CC + 255) / 256, 256>>>(x, x16, x8h, x8l, BB*NN*CC);
    split_b_kernel<<<(3*CC*CC + 255) / 256, 256>>>(w_in, wi16, wi8l, wi8h, 3*CC*CC);
    split_b_kernel<<<(CC*CC + 255) / 256, 256>>>(w_out, wo16, wo8l, wo8h, CC*CC);

    // 2) QKV projection (hybrid bf16/fp8; writes split q/k/v, q pre-scaled)
    gemm_mma_kernel<<<dim3(24, 64), 256, GEMM_SMEM>>>(
        x16, x8h, x8l, wi16, wi8l, wi8h, b_in, nullptr, 0);

    // 3) tensor-core flash attention
    attn_mma_kernel<<<dim3(8, 128), 256, ATTN_SMEM>>>();

    // 4) out projection
    gemm_mma_kernel<<<dim3(8, 64), 256, GEMM_SMEM>>>(
        o16, o8h, o8l, wo16, wo8l, wo8h, b_out, out, 1);
}

// round 10
// speedup vs baseline: 1.0345x; 1.0345x over previous
#include <cuda_runtime.h>
#include <cuda_bf16.h>
#include <cstdint>

// Problem constants: B=8, N=1024, C=1024, H=16, D=64
#define BB 8
#define NN 1024
#define CC 1024
#define HH 16
#define DD 64
#define SCALE 0.125f

// ---------------------------------------------------------------------------
// Scratch
// ---------------------------------------------------------------------------
__device__ __nv_bfloat16 g_qhi[BB*HH*NN*DD];  // [bh][n][d], q pre-scaled by 1/8
__device__ __nv_bfloat16 g_qlo[BB*HH*NN*DD];
__device__ __nv_bfloat16 g_khi[BB*HH*NN*DD];
__device__ __nv_bfloat16 g_klo[BB*HH*NN*DD];
__device__ __nv_bfloat16 g_vhi[BB*HH*NN*DD];
__device__ __nv_bfloat16 g_vlo[BB*HH*NN*DD];

// dual-digit int8 operands for GEMM1: X = (H + L/254) / s, s = 127/amax
__device__ int8_t g_xH[BB*NN*CC];
__device__ int8_t g_xL[BB*NN*CC];
__device__ int8_t g_wiH[3*CC*CC];
__device__ int8_t g_wiL[3*CC*CC];

// bf16 hi/lo operands for GEMM2
__device__ __nv_bfloat16 g_wohi[CC*CC];
__device__ __nv_bfloat16 g_wolo[CC*CC];
__device__ __nv_bfloat16 g_ohi[BB*NN*CC];   // attention out, [B*N, C]
__device__ __nv_bfloat16 g_olo[BB*NN*CC];

// amax registry: 0=x, 1=w_in (bitcast fp32, non-negative)
__device__ unsigned g_amax_u[2];

// ---------------------------------------------------------------------------
// Helpers
// ---------------------------------------------------------------------------
__device__ __forceinline__ uint32_t smem_to_u32(const void* p) {
    uint32_t a;
    asm("{ .reg .u64 t; cvta.to.shared.u64 t, %1; cvt.u32.u64 %0, t; }"
        : "=r"(a) : "l"(p));
    return a;
}
__device__ __forceinline__ void ldsm_x4(uint32_t r[4], uint32_t addr) {
    asm volatile("ldmatrix.sync.aligned.m8n8.x4.shared.b16 {%0,%1,%2,%3}, [%4];"
        : "=r"(r[0]), "=r"(r[1]), "=r"(r[2]), "=r"(r[3]) : "r"(addr));
}
__device__ __forceinline__ void ldsm_x4_t(uint32_t r[4], uint32_t addr) {
    asm volatile("ldmatrix.sync.aligned.m8n8.x4.trans.shared.b16 {%0,%1,%2,%3}, [%4];"
        : "=r"(r[0]), "=r"(r[1]), "=r"(r[2]), "=r"(r[3]) : "r"(addr));
}
__device__ __forceinline__ void mma16816(float c[4], const uint32_t a[4],
                                         const uint32_t b[2]) {
    asm volatile(
        "mma.sync.aligned.m16n8k16.row.col.f32.bf16.bf16.f32 "
        "{%0,%1,%2,%3}, {%4,%5,%6,%7}, {%8,%9}, {%0,%1,%2,%3};"
        : "+f"(c[0]), "+f"(c[1]), "+f"(c[2]), "+f"(c[3])
        : "r"(a[0]), "r"(a[1]), "r"(a[2]), "r"(a[3]), "r"(b[0]), "r"(b[1]));
}
__device__ __forceinline__ void imma16832(int c[4], const uint32_t a[4],
                                          const uint32_t b[2]) {
    asm volatile(
        "mma.sync.aligned.m16n8k32.row.col.s32.s8.s8.s32 "
        "{%0,%1,%2,%3}, {%4,%5,%6,%7}, {%8,%9}, {%0,%1,%2,%3};"
        : "+r"(c[0]), "+r"(c[1]), "+r"(c[2]), "+r"(c[3])
        : "r"(a[0]), "r"(a[1]), "r"(a[2]), "r"(a[3]), "r"(b[0]), "r"(b[1]));
}
#define CP_ASYNC16(sa, ga) \
    asm volatile("cp.async.cg.shared.global [%0], [%1], 16;" \
                 :: "r"(sa), "l"(ga) : "memory")
#define CP_COMMIT() asm volatile("cp.async.commit_group;" ::: "memory")
#define CP_WAIT1()  asm volatile("cp.async.wait_group 1;" ::: "memory")
#define CP_WAIT0()  asm volatile("cp.async.wait_group 0;" ::: "memory")

__device__ __forceinline__ uint32_t swz(int row, int cx) {
    return (uint32_t)(row * 128) + ((uint32_t)(cx ^ (row & 7)) << 4);
}
__device__ __forceinline__ float amax_scale(int idx) {
    float a = __uint_as_float(g_amax_u[idx]);
    return 127.f / (a * 1.0001f + 1e-30f);
}

// ---------------------------------------------------------------------------
// Prep kernels
// ---------------------------------------------------------------------------
__global__ void zero_amax_kernel() {
    if (threadIdx.x < 2) g_amax_u[threadIdx.x] = 0u;
}
__global__ void __launch_bounds__(256) amax_kernel(
        const float* __restrict__ src, int n, int idx) {
    float m = 0.f;
    for (int i = blockIdx.x * 256 + threadIdx.x; i < n; i += gridDim.x * 256)
        m = fmaxf(m, fabsf(src[i]));
#pragma unroll
    for (int off = 16; off > 0; off >>= 1)
        m = fmaxf(m, __shfl_xor_sync(0xffffffffu, m, off));
    if ((threadIdx.x & 31) == 0)
        atomicMax(&g_amax_u[idx], __float_as_uint(m));
}
__global__ void __launch_bounds__(256) quant_kernel(
        const float* __restrict__ src, int8_t* __restrict__ H,
        int8_t* __restrict__ L, int n, int idx) {
    int i = blockIdx.x * 256 + threadIdx.x;
    if (i < n) {
        float s = amax_scale(idx);
        float X = src[i] * s;
        float h = rintf(X);
        float l = rintf((X - h) * 254.f);
        H[i] = (int8_t)(int)h;
        L[i] = (int8_t)(int)l;
    }
}
__global__ void __launch_bounds__(256) split_kernel(
        const float* __restrict__ src, __nv_bfloat16* __restrict__ hi,
        __nv_bfloat16* __restrict__ lo, int n) {
    int i = blockIdx.x * 256 + threadIdx.x;
    if (i < n) {
        float x = src[i];
        __nv_bfloat16 h = __float2bfloat16(x);
        float r = x - __bfloat162float(h);
        hi[i] = h;
        lo[i] = __float2bfloat16(r);
    }
}

// ---------------------------------------------------------------------------
// GEMM1: dual-digit int8 IMMA, D = (A@B^T)/(sA*sB) + bias -> split qkv scatter
// Tile 128x128, K-chunk 64. Smem row (128B): [H k0-63 cx0-3 | L k0-63 cx4-7].
// Per k32 step: 16 IMMA hh + 32 IMMA cross. 3-stage cp.async (96KB), 8 warps.
// ---------------------------------------------------------------------------
#define ISTG 32768
#define IT_B 16384
#define IGEMM_SMEM (3 * ISTG)
#define INV254 0.003937007874f

__global__ void __launch_bounds__(256) gemm_imma_kernel(
        const int8_t* __restrict__ AH, const int8_t* __restrict__ AL,
        const int8_t* __restrict__ BH, const int8_t* __restrict__ BL,
        const float* __restrict__ bias) {
    extern __shared__ char smem[];
    const uint32_t sbase = smem_to_u32(smem);
    const int tid = threadIdx.x;
    const int wid = tid >> 5, lane = tid & 31;
    const int wm = wid >> 2, wn = wid & 3;
    const int row0 = blockIdx.y * 128, col0 = blockIdx.x * 128;
    const int mat = lane >> 3, rin = lane & 7;

    int hh[4][4][4], cr[4][4][4];
#pragma unroll
    for (int mi = 0; mi < 4; mi++)
#pragma unroll
        for (int nj = 0; nj < 4; nj++)
#pragma unroll
            for (int e = 0; e < 4; e++) { hh[mi][nj][e] = 0; cr[mi][nj][e] = 0; }

    auto issue = [&](int stage, int c) {
        const int k0 = c * 64;
        const uint32_t sst = sbase + stage * ISTG;
#pragma unroll
        for (int p = 0; p < 4; p++) {
            int id = tid + p * 256;
            int row = id >> 3, cx = id & 7;
            uint32_t dst = swz(row, cx);
            size_t ra = (size_t)(row0 + row) * 1024 + k0;
            size_t rb = (size_t)(col0 + row) * 1024 + k0;
            const int8_t* pa = (cx < 4) ? (AH + ra + cx * 16) : (AL + ra + (cx - 4) * 16);
            const int8_t* pb = (cx < 4) ? (BH + rb + cx * 16) : (BL + rb + (cx - 4) * 16);
            CP_ASYNC16(sst + dst, pa);
            CP_ASYNC16(sst + IT_B + dst, pb);
        }
        CP_COMMIT();
    };

    auto compute = [&](int stage) {
        const uint32_t sA = sbase + stage * ISTG;
#pragma unroll
        for (int s = 0; s < 2; s++) {
            const int cxh = 2 * s + (mat >> 1);
            const int cxl = cxh + 4;
            uint32_t ah[4][4], al[4][4], bh[4][2], bl[4][2];
#pragma unroll
            for (int mi = 0; mi < 4; mi++) {
                int row = wm * 64 + mi * 16 + (mat & 1) * 8 + rin;
                ldsm_x4(ah[mi], sA + swz(row, cxh));
                ldsm_x4(al[mi], sA + swz(row, cxl));
            }
#pragma unroll
            for (int nf = 0; nf < 2; nf++) {
                int row = wn * 32 + nf * 16 + (mat & 1) * 8 + rin;
                uint32_t t[4];
                ldsm_x4(t, sA + IT_B + swz(row, cxh));
                bh[nf*2][0] = t[0]; bh[nf*2][1] = t[2];
                bh[nf*2+1][0] = t[1]; bh[nf*2+1][1] = t[3];
                ldsm_x4(t, sA + IT_B + swz(row, cxl));
                bl[nf*2][0] = t[0]; bl[nf*2][1] = t[2];
                bl[nf*2+1][0] = t[1]; bl[nf*2+1][1] = t[3];
            }
#pragma unroll
            for (int mi = 0; mi < 4; mi++)
#pragma unroll
                for (int nj = 0; nj < 4; nj++)
                    imma16832(hh[mi][nj], ah[mi], bh[nj]);
#pragma unroll
            for (int mi = 0; mi < 4; mi++)
#pragma unroll
                for (int nj = 0; nj < 4; nj++)
                    imma16832(cr[mi][nj], ah[mi], bl[nj]);
#pragma unroll
            for (int mi = 0; mi < 4; mi++)
#pragma unroll
                for (int nj = 0; nj < 4; nj++)
                    imma16832(cr[mi][nj], al[mi], bh[nj]);
        }
    };

    auto step = [&](int c, int stage, int nxt) {
        if (c < 15) CP_WAIT1(); else CP_WAIT0();
        __syncthreads();
        if (c + 2 < 16) issue(nxt, c + 2);
        compute(stage);
    };

    issue(0, 0); issue(1, 1);
#pragma unroll 1
    for (int cb = 0; cb < 15; cb += 3) {
        step(cb + 0, 0, 2);
        step(cb + 1, 1, 0);
        step(cb + 2, 2, 1);
    }
    step(15, 0, 2);

    // epilogue: scatter bf16 hi/lo q/k/v (q pre-scaled)
    const float invS = 1.f / (amax_scale(0) * amax_scale(1));
    const int g = lane >> 2, c4 = lane & 3;
    const int sec = col0 >> 10;   // uniform per block
#pragma unroll
    for (int mi = 0; mi < 4; mi++)
#pragma unroll
        for (int h2 = 0; h2 < 2; h2++) {
            int row = row0 + wm * 64 + mi * 16 + g + h2 * 8;
            int b = row >> 10, n_ = row & 1023;
#pragma unroll
            for (int nj = 0; nj < 4; nj++) {
                int col = col0 + wn * 32 + nj * 8 + c4 * 2;
                float v0 = ((float)hh[mi][nj][h2*2+0] +
                            (float)cr[mi][nj][h2*2+0] * INV254) * invS + bias[col];
                float v1 = ((float)hh[mi][nj][h2*2+1] +
                            (float)cr[mi][nj][h2*2+1] * INV254) * invS + bias[col+1];
                int ci = col & 1023;
                int hhd = ci >> 6, d = ci & 63;
                if (sec == 0) { v0 *= SCALE; v1 *= SCALE; }
                __nv_bfloat162 hi2 = __floats2bfloat162_rn(v0, v1);
                float r0 = v0 - __bfloat162float(hi2.x);
                float r1 = v1 - __bfloat162float(hi2.y);
                __nv_bfloat162 lo2 = __floats2bfloat162_rn(r0, r1);
                size_t idx = ((size_t)(((b * 16 + hhd) << 10) | n_)) * 64 + d;
                __nv_bfloat16 *dh = (sec == 0) ? g_qhi : (sec == 1) ? g_khi : g_vhi;
                __nv_bfloat16 *dl = (sec == 0) ? g_qlo : (sec == 1) ? g_klo : g_vlo;
                *(uint32_t*)&dh[idx] = *(uint32_t*)&hi2;
                *(uint32_t*)&dl[idx] = *(uint32_t*)&lo2;
            }
        }
}

// ---------------------------------------------------------------------------
// GEMM2: bf16 3-term split (R7 proven). D = A@B^T + bias -> fp32 out.
// Tile 128x128, K-chunk 32, smem row [32 bf16 hi | 32 bf16 lo], 3-stage.
// ---------------------------------------------------------------------------
#define STG_STRIDE 32768
#define T_B 16384
#define GEMM_SMEM (3 * STG_STRIDE)

__global__ void __launch_bounds__(256, 2) gemm_bf16_kernel(
        const __nv_bfloat16* __restrict__ Ahi, const __nv_bfloat16* __restrict__ Alo,
        const __nv_bfloat16* __restrict__ Bhi, const __nv_bfloat16* __restrict__ Blo,
        const float* __restrict__ bias, float* __restrict__ outp) {
    extern __shared__ char smem[];
    const uint32_t sbase = smem_to_u32(smem);
    const int tid = threadIdx.x;
    const int wid = tid >> 5, lane = tid & 31;
    const int wm = wid >> 2, wn = wid & 3;
    const int row0 = blockIdx.y * 128, col0 = blockIdx.x * 128;
    const int mat = lane >> 3, rin = lane & 7;

    float cacc[4][4][4];
#pragma unroll
    for (int mi = 0; mi < 4; mi++)
#pragma unroll
        for (int nj = 0; nj < 4; nj++)
#pragma unroll
            for (int e = 0; e < 4; e++) cacc[mi][nj][e] = 0.f;

    auto issue = [&](int stage, int c) {
        const int k0 = c * 32;
        const uint32_t sst = sbase + stage * STG_STRIDE;
#pragma unroll
        for (int p = 0; p < 4; p++) {
            int id = tid + p * 256;
            int row = id >> 3, cx = id & 7;
            uint32_t dst = swz(row, cx);
            int kg = k0 + (cx & 3) * 8;
            size_t sa = (size_t)(row0 + row) * 1024 + kg;
            size_t sb = (size_t)(col0 + row) * 1024 + kg;
            CP_ASYNC16(sst + dst,       (cx < 4) ? (Ahi + sa) : (Alo + sa));
            CP_ASYNC16(sst + T_B + dst, (cx < 4) ? (Bhi + sb) : (Blo + sb));
        }
        CP_COMMIT();
    };

    auto compute = [&](int stage) {
        const uint32_t sA = sbase + stage * STG_STRIDE;
#pragma unroll
        for (int s = 0; s < 2; s++) {
            uint32_t ah[4][4], al[4][4], bh[4][2], bl[4][2];
            const int cxh = s * 2 + (mat >> 1);
            const int cxl = cxh + 4;
#pragma unroll
            for (int mi = 0; mi < 4; mi++) {
                int row = wm * 64 + mi * 16 + rin + (mat & 1) * 8;
                ldsm_x4(ah[mi], sA + swz(row, cxh));
                ldsm_x4(al[mi], sA + swz(row, cxl));
            }
#pragma unroll
            for (int nf = 0; nf < 2; nf++) {
                int row = wn * 32 + nf * 16 + rin + (mat & 1) * 8;
                uint32_t t[4];
                ldsm_x4(t, sA + T_B + swz(row, cxh));
                bh[nf*2][0] = t[0]; bh[nf*2][1] = t[2];
                bh[nf*2+1][0] = t[1]; bh[nf*2+1][1] = t[3];
                ldsm_x4(t, sA + T_B + swz(row, cxl));
                bl[nf*2][0] = t[0]; bl[nf*2][1] = t[2];
                bl[nf*2+1][0] = t[1]; bl[nf*2+1][1] = t[3];
            }
#pragma unroll
            for (int mi = 0; mi < 4; mi++)
#pragma unroll
                for (int nj = 0; nj < 4; nj++)
                    mma16816(cacc[mi][nj], ah[mi], bh[nj]);
#pragma unroll
            for (int mi = 0; mi < 4; mi++)
#pragma unroll
                for (int nj = 0; nj < 4; nj++)
                    mma16816(cacc[mi][nj], ah[mi], bl[nj]);
#pragma unroll
            for (int mi = 0; mi < 4; mi++)
#pragma unroll
                for (int nj = 0; nj < 4; nj++)
                    mma16816(cacc[mi][nj], al[mi], bh[nj]);
        }
    };

    auto step = [&](int c, int stage, int nxt) {
        if (c < 31) CP_WAIT1(); else CP_WAIT0();
        __syncthreads();
        if (c + 2 < 32) issue(nxt, c + 2);
        compute(stage);
    };

    issue(0, 0); issue(1, 1);
#pragma unroll 1
    for (int cb = 0; cb < 30; cb += 3) {
        step(cb + 0, 0, 2);
        step(cb + 1, 1, 0);
        step(cb + 2, 2, 1);
    }
    step(30, 0, 2);
    step(31, 1, 0);

    const int g = lane >> 2, c4 = lane & 3;
#pragma unroll
    for (int mi = 0; mi < 4; mi++)
#pragma unroll
        for (int h2 = 0; h2 < 2; h2++) {
            int row = row0 + wm * 64 + mi * 16 + g + h2 * 8;
#pragma unroll
            for (int nj = 0; nj < 4; nj++) {
                int col = col0 + wn * 32 + nj * 8 + c4 * 2;
                float v0 = cacc[mi][nj][h2 * 2 + 0] + bias[col];
                float v1 = cacc[mi][nj][h2 * 2 + 1] + bias[col + 1];
                float2 vv = make_float2(v0, v1);
                *(float2*)&outp[(size_t)row * 1024 + col] = vv;
            }
        }
}

// ---------------------------------------------------------------------------
// Tensor-core flash attention (bf16 3-term split — proven R7 mainloop).
// Epilogue writes bf16 hi/lo o into [B*N, C].
// ---------------------------------------------------------------------------
#define AT_SQH 0
#define AT_SQL 16384
#define AT_ST0 32768
#define AT_KH 0
#define AT_KL 8192
#define AT_VH 16384
#define AT_VL 24576
#define ATTN_SMEM 98304

__global__ void __launch_bounds__(256, 2) attn_mma_kernel() {
    extern __shared__ char smem[];
    const uint32_t sbase = smem_to_u32(smem);
    const int tid = threadIdx.x;
    const int wid = tid >> 5, lane = tid & 31;
    const int bh = blockIdx.y, q0 = blockIdx.x * 128;
    const int b = bh >> 4, h = bh & 15;
    const int mat = lane >> 3, rin = lane & 7;
    const int g = lane >> 2, c4 = lane & 3;

    const __nv_bfloat16* __restrict__ qhp = g_qhi + (size_t)bh * NN * DD;
    const __nv_bfloat16* __restrict__ qlp = g_qlo + (size_t)bh * NN * DD;
    const __nv_bfloat16* __restrict__ khp = g_khi + (size_t)bh * NN * DD;
    const __nv_bfloat16* __restrict__ klp = g_klo + (size_t)bh * NN * DD;
    const __nv_bfloat16* __restrict__ vhp = g_vhi + (size_t)bh * NN * DD;
    const __nv_bfloat16* __restrict__ vlp = g_vlo + (size_t)bh * NN * DD;

#pragma unroll
    for (int p = 0; p < 4; p++) {
        int chunk = tid + p * 256;
        int row = chunk >> 3, cx = chunk & 7;
        uint32_t dst = swz(row, cx);
        size_t src = (size_t)(q0 + row) * 64 + cx * 8;
        CP_ASYNC16(sbase + AT_SQH + dst, qhp + src);
        CP_ASYNC16(sbase + AT_SQL + dst, qlp + src);
    }
    CP_COMMIT();

    auto issue_kv = [&](int st, int kt) {
        const uint32_t sb = sbase + AT_ST0 + st * 32768;
        const size_t base = (size_t)(kt * 64) * 64;
#pragma unroll
        for (int p = 0; p < 2; p++) {
            int chunk = tid + p * 256;
            int row = chunk >> 3, cx = chunk & 7;
            uint32_t dst = swz(row, cx);
            size_t src = base + (size_t)row * 64 + cx * 8;
            CP_ASYNC16(sb + AT_KH + dst, khp + src);
            CP_ASYNC16(sb + AT_KL + dst, klp + src);
            CP_ASYNC16(sb + AT_VH + dst, vhp + src);
            CP_ASYNC16(sb + AT_VL + dst, vlp + src);
        }
        CP_COMMIT();
    };
    issue_kv(0, 0);
    issue_kv(1, 1);

    float m0 = -1e30f, m1 = -1e30f, l0 = 0.f, l1 = 0.f;
    float oacc[8][4];
#pragma unroll
    for (int i = 0; i < 8; i++)
#pragma unroll
        for (int e = 0; e < 4; e++) oacc[i][e] = 0.f;

    auto astep = [&](int kt, int st) {
        if (kt < 15) CP_WAIT1(); else CP_WAIT0();
        __syncthreads();
        const uint32_t skv = sbase + AT_ST0 + st * 32768;

        float sacc[8][4];
#pragma unroll
        for (int i = 0; i < 8; i++)
#pragma unroll
            for (int e = 0; e < 4; e++) sacc[i][e] = 0.f;

#pragma unroll
        for (int s = 0; s < 4; s++) {
            const int cx = s * 2 + (mat >> 1);
            uint32_t qh[4], ql[4];
            {
                int row = wid * 16 + (mat & 1) * 8 + rin;
                uint32_t off = swz(row, cx);
                ldsm_x4(qh, sbase + AT_SQH + off);
                ldsm_x4(ql, sbase + AT_SQL + off);
            }
#pragma unroll
            for (int t = 0; t < 4; t++) {
                int krow = t * 16 + (mat & 1) * 8 + rin;
                uint32_t off = swz(krow, cx);
                uint32_t th[4], tl[4];
                ldsm_x4(th, skv + AT_KH + off);
                ldsm_x4(tl, skv + AT_KL + off);
                uint32_t bh0[2] = {th[0], th[2]}, bh1[2] = {th[1], th[3]};
                uint32_t bl0[2] = {tl[0], tl[2]}, bl1[2] = {tl[1], tl[3]};
                mma16816(sacc[2*t],   qh, bh0);
                mma16816(sacc[2*t+1], qh, bh1);
                mma16816(sacc[2*t],   qh, bl0);
                mma16816(sacc[2*t+1], qh, bl1);
                mma16816(sacc[2*t],   ql, bh0);
                mma16816(sacc[2*t+1], ql, bh1);
            }
        }

        float mx0 = -1e30f, mx1 = -1e30f;
#pragma unroll
        for (int i = 0; i < 8; i++) {
            mx0 = fmaxf(mx0, fmaxf(sacc[i][0], sacc[i][1]));
            mx1 = fmaxf(mx1, fmaxf(sacc[i][2], sacc[i][3]));
        }
        mx0 = fmaxf(mx0, __shfl_xor_sync(0xffffffffu, mx0, 1));
        mx0 = fmaxf(mx0, __shfl_xor_sync(0xffffffffu, mx0, 2));
        mx1 = fmaxf(mx1, __shfl_xor_sync(0xffffffffu, mx1, 1));
        mx1 = fmaxf(mx1, __shfl_xor_sync(0xffffffffu, mx1, 2));
        float mn0 = fmaxf(m0, mx0), mn1 = fmaxf(m1, mx1);
        float al0 = __expf(m0 - mn0), al1 = __expf(m1 - mn1);
        m0 = mn0; m1 = mn1;
        float rs0 = 0.f, rs1 = 0.f;
#pragma unroll
        for (int i = 0; i < 8; i++) {
            sacc[i][0] = __expf(sacc[i][0] - mn0);
            sacc[i][1] = __expf(sacc[i][1] - mn0);
            sacc[i][2] = __expf(sacc[i][2] - mn1);
            sacc[i][3] = __expf(sacc[i][3] - mn1);
            rs0 += sacc[i][0] + sacc[i][1];
            rs1 += sacc[i][2] + sacc[i][3];
        }
        rs0 += __shfl_xor_sync(0xffffffffu, rs0, 1);
        rs0 += __shfl_xor_sync(0xffffffffu, rs0, 2);
        rs1 += __shfl_xor_sync(0xffffffffu, rs1, 1);
        rs1 += __shfl_xor_sync(0xffffffffu, rs1, 2);
        l0 = l0 * al0 + rs0;
        l1 = l1 * al1 + rs1;
#pragma unroll
        for (int i = 0; i < 8; i++) {
            oacc[i][0] *= al0; oacc[i][1] *= al0;
            oacc[i][2] *= al1; oacc[i][3] *= al1;
        }

#pragma unroll
        for (int s = 0; s < 4; s++) {
            uint32_t ph[4], pl[4];
            {
                float e0 = sacc[2*s][0], e1 = sacc[2*s][1];
                float e2 = sacc[2*s][2], e3 = sacc[2*s][3];
                float f0 = sacc[2*s+1][0], f1 = sacc[2*s+1][1];
                float f2 = sacc[2*s+1][2], f3 = sacc[2*s+1][3];
                __nv_bfloat162 t0 = __floats2bfloat162_rn(e0, e1);
                __nv_bfloat162 t1 = __floats2bfloat162_rn(e2, e3);
                __nv_bfloat162 t2 = __floats2bfloat162_rn(f0, f1);
                __nv_bfloat162 t3 = __floats2bfloat162_rn(f2, f3);
                ph[0] = *(uint32_t*)&t0; ph[1] = *(uint32_t*)&t1;
                ph[2] = *(uint32_t*)&t2; ph[3] = *(uint32_t*)&t3;
                __nv_bfloat162 u0 = __floats2bfloat162_rn(
                    e0 - __bfloat162float(t0.x), e1 - __bfloat162float(t0.y));
                __nv_bfloat162 u1 = __floats2bfloat162_rn(
                    e2 - __bfloat162float(t1.x), e3 - __bfloat162float(t1.y));
                __nv_bfloat162 u2 = __floats2bfloat162_rn(
                    f0 - __bfloat162float(t2.x), f1 - __bfloat162float(t2.y));
                __nv_bfloat162 u3 = __floats2bfloat162_rn(
                    f2 - __bfloat162float(t3.x), f3 - __bfloat162float(t3.y));
                pl[0] = *(uint32_t*)&u0; pl[1] = *(uint32_t*)&u1;
                pl[2] = *(uint32_t*)&u2; pl[3] = *(uint32_t*)&u3;
            }
#pragma unroll
            for (int t = 0; t < 4; t++) {
                int vrow = s * 16 + (mat >> 1) * 8 + rin;
                int cxv = t * 2 + (mat & 1);
                uint32_t off = swz(vrow, cxv);
                uint32_t th[4], tl[4];
                ldsm_x4_t(th, skv + AT_VH + off);
                ldsm_x4_t(tl, skv + AT_VL + off);
                uint32_t vh0[2] = {th[0], th[2]}, vh1[2] = {th[1], th[3]};
                uint32_t vl0[2] = {tl[0], tl[2]}, vl1[2] = {tl[1], tl[3]};
                mma16816(oacc[2*t],   ph, vh0);
                mma16816(oacc[2*t+1], ph, vh1);
                mma16816(oacc[2*t],   ph, vl0);
                mma16816(oacc[2*t+1], ph, vl1);
                mma16816(oacc[2*t],   pl, vh0);
                mma16816(oacc[2*t+1], pl, vh1);
            }
        }
        __syncthreads();
        if (kt + 2 < 16) issue_kv(st, kt + 2);
    };

#pragma unroll 1
    for (int kt = 0; kt < 16; kt += 2) {
        astep(kt, 0);
        astep(kt + 1, 1);
    }

    // epilogue: normalize, split bf16 hi/lo, write [B*N, C]
    float inv0 = 1.f / l0, inv1 = 1.f / l1;
    int r0 = q0 + wid * 16 + g;
    int r1 = r0 + 8;
#pragma unroll
    for (int nj = 0; nj < 8; nj++) {
        int col = h * 64 + nj * 8 + c4 * 2;
        {
            float v0 = oacc[nj][0] * inv0, v1 = oacc[nj][1] * inv0;
            __nv_bfloat162 hi2 = __floats2bfloat162_rn(v0, v1);
            __nv_bfloat162 lo2 = __floats2bfloat162_rn(
                v0 - __bfloat162float(hi2.x), v1 - __bfloat162float(hi2.y));
            size_t idx = (size_t)(b * 1024 + r0) * 1024 + col;
            *(uint32_t*)&g_ohi[idx] = *(uint32_t*)&hi2;
            *(uint32_t*)&g_olo[idx] = *(uint32_t*)&lo2;
        }
        {
            float v0 = oacc[nj][2] * inv1, v1 = oacc[nj][3] * inv1;
            __nv_bfloat162 hi2 = __floats2bfloat162_rn(v0, v1);
            __nv_bfloat162 lo2 = __floats2bfloat162_rn(
                v0 - __bfloat162float(hi2.x), v1 - __bfloat162float(hi2.y));
            size_t idx = (size_t)(b * 1024 + r1) * 1024 + col;
            *(uint32_t*)&g_ohi[idx] = *(uint32_t*)&hi2;
            *(uint32_t*)&g_olo[idx] = *(uint32_t*)&lo2;
        }
    }
}

// ---------------------------------------------------------------------------
extern "C" void kernel_launch(void* const* d_in, const int* in_sizes, int n_in,
                              void* d_out, int out_size) {
    const float* x     = (const float*)d_in[0];
    const float* w_in  = (const float*)d_in[1];
    const float* b_in  = (const float*)d_in[2];
    const float* w_out = (const float*)d_in[3];
    const float* b_out = (const float*)d_in[4];
    float* out = (float*)d_out;

    static bool attr_set = false;
    if (!attr_set) {
        cudaFuncSetAttribute(gemm_imma_kernel,
                             cudaFuncAttributeMaxDynamicSharedMemorySize, IGEMM_SMEM);
        cudaFuncSetAttribute(gemm_bf16_kernel,
                             cudaFuncAttributeMaxDynamicSharedMemorySize, GEMM_SMEM);
        cudaFuncSetAttribute(attn_mma_kernel,
                             cudaFuncAttributeMaxDynamicSharedMemorySize, ATTN_SMEM);
        attr_set = true;
    }

    int8_t *xH, *xL, *wiH, *wiL;
    __nv_bfloat16 *wohi, *wolo, *ohi, *olo;
    cudaGetSymbolAddress((void**)&xH,   g_xH);
    cudaGetSymbolAddress((void**)&xL,   g_xL);
    cudaGetSymbolAddress((void**)&wiH,  g_wiH);
    cudaGetSymbolAddress((void**)&wiL,  g_wiL);
    cudaGetSymbolAddress((void**)&wohi, g_wohi);
    cudaGetSymbolAddress((void**)&wolo, g_wolo);
    cudaGetSymbolAddress((void**)&ohi,  g_ohi);
    cudaGetSymbolAddress((void**)&olo,  g_olo);

    const int nx = BB*NN*CC, nwi = 3*CC*CC, nwo = CC*CC;

    // 1) prep: amax + int8 quant (GEMM1), bf16 split (GEMM2 weights)
    zero_amax_kernel<<<1, 32>>>();
    amax_kernel<<<512, 256>>>(x, nx, 0);
    amax_kernel<<<512, 256>>>(w_in, nwi, 1);
    quant_kernel<<<(nx + 255) / 256, 256>>>(x, xH, xL, nx, 0);
    quant_kernel<<<(nwi + 255) / 256, 256>>>(w_in, wiH, wiL, nwi, 1);
    split_kernel<<<(nwo + 255) / 256, 256>>>(w_out, wohi, wolo, nwo);

    // 2) QKV projection (dual int8 IMMA)
    gemm_imma_kernel<<<dim3(24, 64), 256, IGEMM_SMEM>>>(
        xH, xL, wiH, wiL, b_in);

    // 3) tensor-core flash attention (bf16 split)
    attn_mma_kernel<<<dim3(8, 128), 256, ATTN_SMEM>>>();

    // 4) out projection (bf16 split)
    gemm_bf16_kernel<<<dim3(8, 64), 256, GEMM_SMEM>>>(
        ohi, olo, wohi, wolo, b_out, out);
}

// round 11
// speedup vs baseline: 2.3769x; 2.2977x over previous
#include <cuda_runtime.h>
#include <cuda_bf16.h>
#include <cuda_fp16.h>
#include <cstdint>

// Problem constants: B=8, N=1024, C=1024, H=16, D=64
#define BB 8
#define NN 1024
#define CC 1024
#define HH 16
#define DD 64
#define SCALE 0.125f

// ---------------------------------------------------------------------------
// Scratch
// ---------------------------------------------------------------------------
__device__ __nv_bfloat16 g_qhi[BB*HH*NN*DD];  // [bh][n][d], q pre-scaled by 1/8
__device__ __nv_bfloat16 g_qlo[BB*HH*NN*DD];
__device__ __nv_bfloat16 g_khi[BB*HH*NN*DD];
__device__ __nv_bfloat16 g_klo[BB*HH*NN*DD];
__device__ __nv_bfloat16 g_vhi[BB*HH*NN*DD];
__device__ __nv_bfloat16 g_vlo[BB*HH*NN*DD];

// fp16 operands: A dual (hi+lo, ~22-bit exact), B single fp16
__device__ __half g_xh[BB*NN*CC];
__device__ __half g_xl[BB*NN*CC];
__device__ __half g_wi[3*CC*CC];
__device__ __half g_wo[CC*CC];
__device__ __half g_oh[BB*NN*CC];   // attention out hi, [B*N, C]
__device__ __half g_ol[BB*NN*CC];   // attention out lo

// ---------------------------------------------------------------------------
// Helpers
// ---------------------------------------------------------------------------
__device__ __forceinline__ uint32_t smem_to_u32(const void* p) {
    uint32_t a;
    asm("{ .reg .u64 t; cvta.to.shared.u64 t, %1; cvt.u32.u64 %0, t; }"
        : "=r"(a) : "l"(p));
    return a;
}
__device__ __forceinline__ void ldsm_x4(uint32_t r[4], uint32_t addr) {
    asm volatile("ldmatrix.sync.aligned.m8n8.x4.shared.b16 {%0,%1,%2,%3}, [%4];"
        : "=r"(r[0]), "=r"(r[1]), "=r"(r[2]), "=r"(r[3]) : "r"(addr));
}
__device__ __forceinline__ void ldsm_x4_t(uint32_t r[4], uint32_t addr) {
    asm volatile("ldmatrix.sync.aligned.m8n8.x4.trans.shared.b16 {%0,%1,%2,%3}, [%4];"
        : "=r"(r[0]), "=r"(r[1]), "=r"(r[2]), "=r"(r[3]) : "r"(addr));
}
// bf16 HMMA (attention)
__device__ __forceinline__ void mma16816(float c[4], const uint32_t a[4],
                                         const uint32_t b[2]) {
    asm volatile(
        "mma.sync.aligned.m16n8k16.row.col.f32.bf16.bf16.f32 "
        "{%0,%1,%2,%3}, {%4,%5,%6,%7}, {%8,%9}, {%0,%1,%2,%3};"
        : "+f"(c[0]), "+f"(c[1]), "+f"(c[2]), "+f"(c[3])
        : "r"(a[0]), "r"(a[1]), "r"(a[2]), "r"(a[3]), "r"(b[0]), "r"(b[1]));
}
// fp16 HMMA (GEMMs)
__device__ __forceinline__ void mma16816h(float c[4], const uint32_t a[4],
                                          const uint32_t b[2]) {
    asm volatile(
        "mma.sync.aligned.m16n8k16.row.col.f32.f16.f16.f32 "
        "{%0,%1,%2,%3}, {%4,%5,%6,%7}, {%8,%9}, {%0,%1,%2,%3};"
        : "+f"(c[0]), "+f"(c[1]), "+f"(c[2]), "+f"(c[3])
        : "r"(a[0]), "r"(a[1]), "r"(a[2]), "r"(a[3]), "r"(b[0]), "r"(b[1]));
}
#define CP_ASYNC16(sa, ga) \
    asm volatile("cp.async.cg.shared.global [%0], [%1], 16;" \
                 :: "r"(sa), "l"(ga) : "memory")
#define CP_COMMIT() asm volatile("cp.async.commit_group;" ::: "memory")
#define CP_WAIT1()  asm volatile("cp.async.wait_group 1;" ::: "memory")
#define CP_WAIT0()  asm volatile("cp.async.wait_group 0;" ::: "memory")

__device__ __forceinline__ uint32_t swz(int row, int cx) {
    return (uint32_t)(row * 128) + ((uint32_t)(cx ^ (row & 7)) << 4);
}

// ---------------------------------------------------------------------------
// Prep kernels
// ---------------------------------------------------------------------------
__global__ void __launch_bounds__(256) split_fp16_kernel(
        const float* __restrict__ src, __half* __restrict__ hi,
        __half* __restrict__ lo, int n) {
    int i = blockIdx.x * 256 + threadIdx.x;
    if (i < n) {
        float x = src[i];
        __half h = __float2half(x);
        hi[i] = h;
        lo[i] = __float2half(x - __half2float(h));
    }
}
__global__ void __launch_bounds__(256) cvt_fp16_kernel(
        const float* __restrict__ src, __half* __restrict__ dst, int n) {
    int i = blockIdx.x * 256 + threadIdx.x;
    if (i < n) dst[i] = __float2half(src[i]);
}

// ---------------------------------------------------------------------------
// fp16 asymmetric-split GEMM: D = (Ahi+Alo) @ B^T + bias
// Tile 128x128, K-chunk 32. A smem row (128B) = [32 f16 hi | 32 f16 lo],
// B tile uses cx0-3 only (32 f16/row). 4 HMMA per k32 per warp-tile pair.
// 3-stage cp.async (96KB) -> 2 CTAs/SM, 1 sync per chunk.
// mode 0: scatter qkv (bf16 hi/lo; q scaled); mode 1: fp32 out.
// ---------------------------------------------------------------------------
#define STG_STRIDE 32768
#define T_B 16384
#define GEMM_SMEM (3 * STG_STRIDE)

__global__ void __launch_bounds__(256, 2) gemm_fp16_kernel(
        const __half* __restrict__ Ahi, const __half* __restrict__ Alo,
        const __half* __restrict__ Bw,
        const float* __restrict__ bias, float* __restrict__ outp, int mode) {
    extern __shared__ char smem[];
    const uint32_t sbase = smem_to_u32(smem);
    const int tid = threadIdx.x;
    const int wid = tid >> 5, lane = tid & 31;
    const int wm = wid >> 2, wn = wid & 3;
    const int row0 = blockIdx.y * 128, col0 = blockIdx.x * 128;
    const int mat = lane >> 3, rin = lane & 7;

    float cacc[4][4][4];
#pragma unroll
    for (int mi = 0; mi < 4; mi++)
#pragma unroll
        for (int nj = 0; nj < 4; nj++)
#pragma unroll
            for (int e = 0; e < 4; e++) cacc[mi][nj][e] = 0.f;

    // loader: A 1024 chunks (hi cx0-3, lo cx4-7), B 512 chunks (cx0-3)
    auto issue = [&](int stage, int c) {
        const int k0 = c * 32;
        const uint32_t sst = sbase + stage * STG_STRIDE;
#pragma unroll
        for (int p = 0; p < 4; p++) {
            int id = tid + p * 256;
            int row = id >> 3, cx = id & 7;
            uint32_t dst = swz(row, cx);
            int kg = k0 + (cx & 3) * 8;
            size_t sa = (size_t)(row0 + row) * 1024 + kg;
            CP_ASYNC16(sst + dst, (cx < 4) ? (Ahi + sa) : (Alo + sa));
        }
#pragma unroll
        for (int p = 0; p < 2; p++) {
            int id = tid + p * 256;
            int row = id >> 2, cx = id & 3;
            uint32_t dst = swz(row, cx);
            size_t sb = (size_t)(col0 + row) * 1024 + k0 + cx * 8;
            CP_ASYNC16(sst + T_B + dst, Bw + sb);
        }
        CP_COMMIT();
    };

    auto compute = [&](int stage) {
        const uint32_t sA = sbase + stage * STG_STRIDE;
#pragma unroll
        for (int s = 0; s < 2; s++) {
            uint32_t ah[4][4], al[4][4], bf[4][2];
            const int cxh = s * 2 + (mat >> 1);
            const int cxl = cxh + 4;
#pragma unroll
            for (int mi = 0; mi < 4; mi++) {
                int row = wm * 64 + mi * 16 + rin + (mat & 1) * 8;
                ldsm_x4(ah[mi], sA + swz(row, cxh));
                ldsm_x4(al[mi], sA + swz(row, cxl));
            }
#pragma unroll
            for (int nf = 0; nf < 2; nf++) {
                int row = wn * 32 + nf * 16 + rin + (mat & 1) * 8;
                uint32_t t[4];
                ldsm_x4(t, sA + T_B + swz(row, cxh));
                bf[nf*2][0] = t[0]; bf[nf*2][1] = t[2];
                bf[nf*2+1][0] = t[1]; bf[nf*2+1][1] = t[3];
            }
#pragma unroll
            for (int mi = 0; mi < 4; mi++)
#pragma unroll
                for (int nj = 0; nj < 4; nj++)
                    mma16816h(cacc[mi][nj], ah[mi], bf[nj]);
#pragma unroll
            for (int mi = 0; mi < 4; mi++)
#pragma unroll
                for (int nj = 0; nj < 4; nj++)
                    mma16816h(cacc[mi][nj], al[mi], bf[nj]);
        }
    };

    auto step = [&](int c, int stage, int nxt) {
        if (c < 31) CP_WAIT1(); else CP_WAIT0();
        __syncthreads();
        if (c + 2 < 32) issue(nxt, c + 2);
        compute(stage);
    };

    issue(0, 0); issue(1, 1);
#pragma unroll 1
    for (int cb = 0; cb < 30; cb += 3) {
        step(cb + 0, 0, 2);
        step(cb + 1, 1, 0);
        step(cb + 2, 2, 1);
    }
    step(30, 0, 2);
    step(31, 1, 0);

    const int g = lane >> 2, c4 = lane & 3;
#pragma unroll
    for (int mi = 0; mi < 4; mi++)
#pragma unroll
        for (int h2 = 0; h2 < 2; h2++) {
            int row = row0 + wm * 64 + mi * 16 + g + h2 * 8;
            int b = row >> 10, n_ = row & 1023;
#pragma unroll
            for (int nj = 0; nj < 4; nj++) {
                int col = col0 + wn * 32 + nj * 8 + c4 * 2;
                float v0 = cacc[mi][nj][h2 * 2 + 0] + bias[col];
                float v1 = cacc[mi][nj][h2 * 2 + 1] + bias[col + 1];
                if (mode == 0) {
                    int sec = col >> 10;
                    int ci = col & 1023;
                    int hh = ci >> 6, d = ci & 63;
                    if (sec == 0) { v0 *= SCALE; v1 *= SCALE; }
                    __nv_bfloat162 hi2 = __floats2bfloat162_rn(v0, v1);
                    float r0 = v0 - __bfloat162float(hi2.x);
                    float r1 = v1 - __bfloat162float(hi2.y);
                    __nv_bfloat162 lo2 = __floats2bfloat162_rn(r0, r1);
                    size_t idx = ((size_t)(((b * 16 + hh) << 10) | n_)) * 64 + d;
                    __nv_bfloat16 *dh = (sec == 0) ? g_qhi : (sec == 1) ? g_khi : g_vhi;
                    __nv_bfloat16 *dl = (sec == 0) ? g_qlo : (sec == 1) ? g_klo : g_vlo;
                    *(uint32_t*)&dh[idx] = *(uint32_t*)&hi2;
                    *(uint32_t*)&dl[idx] = *(uint32_t*)&lo2;
                } else {
                    float2 vv = make_float2(v0, v1);
                    *(float2*)&outp[(size_t)row * 1024 + col] = vv;
                }
            }
        }
}

// ---------------------------------------------------------------------------
// Tensor-core flash attention (bf16 3-term split — proven mainloop).
// Epilogue writes fp16 hi/lo o into [B*N, C] for the fp16 out-projection.
// ---------------------------------------------------------------------------
#define AT_SQH 0
#define AT_SQL 16384
#define AT_ST0 32768
#define AT_KH 0
#define AT_KL 8192
#define AT_VH 16384
#define AT_VL 24576
#define ATTN_SMEM 98304

__global__ void __launch_bounds__(256, 2) attn_mma_kernel() {
    extern __shared__ char smem[];
    const uint32_t sbase = smem_to_u32(smem);
    const int tid = threadIdx.x;
    const int wid = tid >> 5, lane = tid & 31;
    const int bh = blockIdx.y, q0 = blockIdx.x * 128;
    const int b = bh >> 4, h = bh & 15;
    const int mat = lane >> 3, rin = lane & 7;
    const int g = lane >> 2, c4 = lane & 3;

    const __nv_bfloat16* __restrict__ qhp = g_qhi + (size_t)bh * NN * DD;
    const __nv_bfloat16* __restrict__ qlp = g_qlo + (size_t)bh * NN * DD;
    const __nv_bfloat16* __restrict__ khp = g_khi + (size_t)bh * NN * DD;
    const __nv_bfloat16* __restrict__ klp = g_klo + (size_t)bh * NN * DD;
    const __nv_bfloat16* __restrict__ vhp = g_vhi + (size_t)bh * NN * DD;
    const __nv_bfloat16* __restrict__ vlp = g_vlo + (size_t)bh * NN * DD;

#pragma unroll
    for (int p = 0; p < 4; p++) {
        int chunk = tid + p * 256;
        int row = chunk >> 3, cx = chunk & 7;
        uint32_t dst = swz(row, cx);
        size_t src = (size_t)(q0 + row) * 64 + cx * 8;
        CP_ASYNC16(sbase + AT_SQH + dst, qhp + src);
        CP_ASYNC16(sbase + AT_SQL + dst, qlp + src);
    }
    CP_COMMIT();

    auto issue_kv = [&](int st, int kt) {
        const uint32_t sb = sbase + AT_ST0 + st * 32768;
        const size_t base = (size_t)(kt * 64) * 64;
#pragma unroll
        for (int p = 0; p < 2; p++) {
            int chunk = tid + p * 256;
            int row = chunk >> 3, cx = chunk & 7;
            uint32_t dst = swz(row, cx);
            size_t src = base + (size_t)row * 64 + cx * 8;
            CP_ASYNC16(sb + AT_KH + dst, khp + src);
            CP_ASYNC16(sb + AT_KL + dst, klp + src);
            CP_ASYNC16(sb + AT_VH + dst, vhp + src);
            CP_ASYNC16(sb + AT_VL + dst, vlp + src);
        }
        CP_COMMIT();
    };
    issue_kv(0, 0);
    issue_kv(1, 1);

    float m0 = -1e30f, m1 = -1e30f, l0 = 0.f, l1 = 0.f;
    float oacc[8][4];
#pragma unroll
    for (int i = 0; i < 8; i++)
#pragma unroll
        for (int e = 0; e < 4; e++) oacc[i][e] = 0.f;

    auto astep = [&](int kt, int st) {
        if (kt < 15) CP_WAIT1(); else CP_WAIT0();
        __syncthreads();
        const uint32_t skv = sbase + AT_ST0 + st * 32768;

        float sacc[8][4];
#pragma unroll
        for (int i = 0; i < 8; i++)
#pragma unroll
            for (int e = 0; e < 4; e++) sacc[i][e] = 0.f;

#pragma unroll
        for (int s = 0; s < 4; s++) {
            const int cx = s * 2 + (mat >> 1);
            uint32_t qh[4], ql[4];
            {
                int row = wid * 16 + (mat & 1) * 8 + rin;
                uint32_t off = swz(row, cx);
                ldsm_x4(qh, sbase + AT_SQH + off);
                ldsm_x4(ql, sbase + AT_SQL + off);
            }
#pragma unroll
            for (int t = 0; t < 4; t++) {
                int krow = t * 16 + (mat & 1) * 8 + rin;
                uint32_t off = swz(krow, cx);
                uint32_t th[4], tl[4];
                ldsm_x4(th, skv + AT_KH + off);
                ldsm_x4(tl, skv + AT_KL + off);
                uint32_t bh0[2] = {th[0], th[2]}, bh1[2] = {th[1], th[3]};
                uint32_t bl0[2] = {tl[0], tl[2]}, bl1[2] = {tl[1], tl[3]};
                mma16816(sacc[2*t],   qh, bh0);
                mma16816(sacc[2*t+1], qh, bh1);
                mma16816(sacc[2*t],   qh, bl0);
                mma16816(sacc[2*t+1], qh, bl1);
                mma16816(sacc[2*t],   ql, bh0);
                mma16816(sacc[2*t+1], ql, bh1);
            }
        }

        float mx0 = -1e30f, mx1 = -1e30f;
#pragma unroll
        for (int i = 0; i < 8; i++) {
            mx0 = fmaxf(mx0, fmaxf(sacc[i][0], sacc[i][1]));
            mx1 = fmaxf(mx1, fmaxf(sacc[i][2], sacc[i][3]));
        }
        mx0 = fmaxf(mx0, __shfl_xor_sync(0xffffffffu, mx0, 1));
        mx0 = fmaxf(mx0, __shfl_xor_sync(0xffffffffu, mx0, 2));
        mx1 = fmaxf(mx1, __shfl_xor_sync(0xffffffffu, mx1, 1));
        mx1 = fmaxf(mx1, __shfl_xor_sync(0xffffffffu, mx1, 2));
        float mn0 = fmaxf(m0, mx0), mn1 = fmaxf(m1, mx1);
        float al0 = __expf(m0 - mn0), al1 = __expf(m1 - mn1);
        m0 = mn0; m1 = mn1;
        float rs0 = 0.f, rs1 = 0.f;
#pragma unroll
        for (int i = 0; i < 8; i++) {
            sacc[i][0] = __expf(sacc[i][0] - mn0);
            sacc[i][1] = __expf(sacc[i][1] - mn0);
            sacc[i][2] = __expf(sacc[i][2] - mn1);
            sacc[i][3] = __expf(sacc[i][3] - mn1);
            rs0 += sacc[i][0] + sacc[i][1];
            rs1 += sacc[i][2] + sacc[i][3];
        }
        rs0 += __shfl_xor_sync(0xffffffffu, rs0, 1);
        rs0 += __shfl_xor_sync(0xffffffffu, rs0, 2);
        rs1 += __shfl_xor_sync(0xffffffffu, rs1, 1);
        rs1 += __shfl_xor_sync(0xffffffffu, rs1, 2);
        l0 = l0 * al0 + rs0;
        l1 = l1 * al1 + rs1;
#pragma unroll
        for (int i = 0; i < 8; i++) {
            oacc[i][0] *= al0; oacc[i][1] *= al0;
            oacc[i][2] *= al1; oacc[i][3] *= al1;
        }

#pragma unroll
        for (int s = 0; s < 4; s++) {
            uint32_t ph[4], pl[4];
            {
                float e0 = sacc[2*s][0], e1 = sacc[2*s][1];
                float e2 = sacc[2*s][2], e3 = sacc[2*s][3];
                float f0 = sacc[2*s+1][0], f1 = sacc[2*s+1][1];
                float f2 = sacc[2*s+1][2], f3 = sacc[2*s+1][3];
                __nv_bfloat162 t0 = __floats2bfloat162_rn(e0, e1);
                __nv_bfloat162 t1 = __floats2bfloat162_rn(e2, e3);
                __nv_bfloat162 t2 = __floats2bfloat162_rn(f0, f1);
                __nv_bfloat162 t3 = __floats2bfloat162_rn(f2, f3);
                ph[0] = *(uint32_t*)&t0; ph[1] = *(uint32_t*)&t1;
                ph[2] = *(uint32_t*)&t2; ph[3] = *(uint32_t*)&t3;
                __nv_bfloat162 u0 = __floats2bfloat162_rn(
                    e0 - __bfloat162float(t0.x), e1 - __bfloat162float(t0.y));
                __nv_bfloat162 u1 = __floats2bfloat162_rn(
                    e2 - __bfloat162float(t1.x), e3 - __bfloat162float(t1.y));
                __nv_bfloat162 u2 = __floats2bfloat162_rn(
                    f0 - __bfloat162float(t2.x), f1 - __bfloat162float(t2.y));
                __nv_bfloat162 u3 = __floats2bfloat162_rn(
                    f2 - __bfloat162float(t3.x), f3 - __bfloat162float(t3.y));
                pl[0] = *(uint32_t*)&u0; pl[1] = *(uint32_t*)&u1;
                pl[2] = *(uint32_t*)&u2; pl[3] = *(uint32_t*)&u3;
            }
#pragma unroll
            for (int t = 0; t < 4; t++) {
                int vrow = s * 16 + (mat >> 1) * 8 + rin;
                int cxv = t * 2 + (mat & 1);
                uint32_t off = swz(vrow, cxv);
                uint32_t th[4], tl[4];
                ldsm_x4_t(th, skv + AT_VH + off);
                ldsm_x4_t(tl, skv + AT_VL + off);
                uint32_t vh0[2] = {th[0], th[2]}, vh1[2] = {th[1], th[3]};
                uint32_t vl0[2] = {tl[0], tl[2]}, vl1[2] = {tl[1], tl[3]};
                mma16816(oacc[2*t],   ph, vh0);
                mma16816(oacc[2*t+1], ph, vh1);
                mma16816(oacc[2*t],   ph, vl0);
                mma16816(oacc[2*t+1], ph, vl1);
                mma16816(oacc[2*t],   pl, vh0);
                mma16816(oacc[2*t+1], pl, vh1);
            }
        }
        __syncthreads();
        if (kt + 2 < 16) issue_kv(st, kt + 2);
    };

#pragma unroll 1
    for (int kt = 0; kt < 16; kt += 2) {
        astep(kt, 0);
        astep(kt + 1, 1);
    }

    // epilogue: normalize, split fp16 hi/lo, write [B*N, C]
    float inv0 = 1.f / l0, inv1 = 1.f / l1;
    int r0 = q0 + wid * 16 + g;
    int r1 = r0 + 8;
#pragma unroll
    for (int nj = 0; nj < 8; nj++) {
        int col = h * 64 + nj * 8 + c4 * 2;
        {
            float v0 = oacc[nj][0] * inv0, v1 = oacc[nj][1] * inv0;
            __half2 hi2 = __floats2half2_rn(v0, v1);
            __half2 lo2 = __floats2half2_rn(
                v0 - __half2float(__low2half(hi2)),
                v1 - __half2float(__high2half(hi2)));
            size_t idx = (size_t)(b * 1024 + r0) * 1024 + col;
            *(uint32_t*)&g_oh[idx] = *(uint32_t*)&hi2;
            *(uint32_t*)&g_ol[idx] = *(uint32_t*)&lo2;
        }
        {
            float v0 = oacc[nj][2] * inv1, v1 = oacc[nj][3] * inv1;
            __half2 hi2 = __floats2half2_rn(v0, v1);
            __half2 lo2 = __floats2half2_rn(
                v0 - __half2float(__low2half(hi2)),
                v1 - __half2float(__high2half(hi2)));
            size_t idx = (size_t)(b * 1024 + r1) * 1024 + col;
            *(uint32_t*)&g_oh[idx] = *(uint32_t*)&hi2;
            *(uint32_t*)&g_ol[idx] = *(uint32_t*)&lo2;
        }
    }
}

// ---------------------------------------------------------------------------
extern "C" void kernel_launch(void* const* d_in, const int* in_sizes, int n_in,
                              void* d_out, int out_size) {
    const float* x     = (const float*)d_in[0];
    const float* w_in  = (const float*)d_in[1];
    const float* b_in  = (const float*)d_in[2];
    const float* w_out = (const float*)d_in[3];
    const float* b_out = (const float*)d_in[4];
    float* out = (float*)d_out;

    static bool attr_set = false;
    if (!attr_set) {
        cudaFuncSetAttribute(gemm_fp16_kernel,
                             cudaFuncAttributeMaxDynamicSharedMemorySize, GEMM_SMEM);
        cudaFuncSetAttribute(attn_mma_kernel,
                             cudaFuncAttributeMaxDynamicSharedMemorySize, ATTN_SMEM);
        attr_set = true;
    }

    __half *xh, *xl, *wi, *wo, *oh, *ol;
    cudaGetSymbolAddress((void**)&xh, g_xh);
    cudaGetSymbolAddress((void**)&xl, g_xl);
    cudaGetSymbolAddress((void**)&wi, g_wi);
    cudaGetSymbolAddress((void**)&wo, g_wo);
    cudaGetSymbolAddress((void**)&oh, g_oh);
    cudaGetSymbolAddress((void**)&ol, g_ol);

    const int nx = BB*NN*CC, nwi = 3*CC*CC, nwo = CC*CC;

    // 1) prep: fp16 dual-split of x; fp16 casts of weights
    split_fp16_kernel<<<(nx + 255) / 256, 256>>>(x, xh, xl, nx);
    cvt_fp16_kernel<<<(nwi + 255) / 256, 256>>>(w_in, wi, nwi);
    cvt_fp16_kernel<<<(nwo + 255) / 256, 256>>>(w_out, wo, nwo);

    // 2) QKV projection (fp16 asymmetric split; writes bf16 split q/k/v)
    gemm_fp16_kernel<<<dim3(24, 64), 256, GEMM_SMEM>>>(
        xh, xl, wi, b_in, nullptr, 0);

    // 3) tensor-core flash attention (bf16 split)
    attn_mma_kernel<<<dim3(8, 128), 256, ATTN_SMEM>>>();

    // 4) out projection (fp16 asymmetric split)
    gemm_fp16_kernel<<<dim3(8, 64), 256, GEMM_SMEM>>>(
        oh, ol, wo, b_out, out, 1);
}